// round 6
// baseline (speedup 1.0000x reference)
#include <cuda_runtime.h>
#include <cstdint>
#include <math_constants.h>

// feat [N, C, 16, 8], scoremap [N, 13, 16, 8], conf [N, 13]
#define KP        13
#define HW        128       // 16*8 spatial
#define SPT       64        // total spatial pairs (f32x2 packing)
#define CPB       128       // channels per block (1 per thread)
#define THREADS   128
#define SPC       16        // spatial pairs per chunk
#define NCHUNK    (SPT / SPC)
#define FSTRIDE   (CPB + 1) // float2 per feat smem row
#define SCS       18        // u64 per score smem row (13 pad to 18: 144B, 16B-aligned)

// ---------- f32x2 helpers (Blackwell packed fp32) ----------
__device__ __forceinline__ unsigned long long pack2(float a, float b) {
    unsigned long long r;
    asm("mov.b64 %0, {%1, %2};" : "=l"(r) : "f"(a), "f"(b));
    return r;
}
__device__ __forceinline__ float2 unpack2(unsigned long long v) {
    float2 f;
    asm("mov.b64 {%0, %1}, %2;" : "=f"(f.x), "=f"(f.y) : "l"(v));
    return f;
}
__device__ __forceinline__ unsigned long long fma2(unsigned long long a,
                                                   unsigned long long b,
                                                   unsigned long long c) {
    unsigned long long d;
    asm("fma.rn.f32x2 %0, %1, %2, %3;" : "=l"(d) : "l"(a), "l"(b), "l"(c));
    return d;
}
__device__ __forceinline__ unsigned long long add2(unsigned long long a,
                                                   unsigned long long b) {
    unsigned long long d;
    asm("add.rn.f32x2 %0, %1, %2;" : "=l"(d) : "l"(a), "l"(b));
    return d;
}

// smem: [ score: SPT x SCS u64 = 9216 B ][ feat: SPC x FSTRIDE float2 = 16512 B ]
#define SMEM_BYTES (SPT * SCS * 8 + SPC * FSTRIDE * 8)

__global__ __launch_bounds__(THREADS, 8)   // force <=64 regs -> 8 blocks/SM
void horeid_kernel(const float* __restrict__ feat,
                   const float* __restrict__ score,
                   const float* __restrict__ conf,
                   float* __restrict__ out_feat,   // [N, 14, C]
                   float* __restrict__ out_conf,   // [N, 14]
                   int C)
{
    extern __shared__ unsigned char smem_raw[];
    unsigned long long* s_sc = (unsigned long long*)smem_raw;       // [SPT][SCS]
    float2* s_ft = (float2*)(smem_raw + SPT * SCS * 8);             // [SPC][FSTRIDE]

    const int tid = threadIdx.x;
    const int n   = blockIdx.y;
    const int c0  = blockIdx.x * CPB;

    // ---- tiny conf normalization, one thread of blockIdx.x==0 ----
    if (blockIdx.x == 0 && tid == 0) {
        const float* cp = conf + (size_t)n * KP;
        float s = 0.0f;
        #pragma unroll
        for (int k = 0; k < KP; k++) s += fabsf(cp[k]);
        s = fmaxf(s, 1e-12f);
        float* oc = out_conf + (size_t)n * (KP + 1);
        #pragma unroll
        for (int k = 0; k < KP; k++) oc[k] = cp[k] / s;
        oc[KP] = 1.0f;
    }

    // ---- stage all scoremap[n] once: s_sc[sp][k] = (score[k][2sp], score[k][2sp+1]) ----
    const float2* g_sc = (const float2*)(score + (size_t)n * KP * HW);
    for (int i = tid; i < KP * SPT; i += THREADS) {
        int k  = i >> 6;          // 0..12
        int sp = i & 63;
        float2 v = g_sc[i];
        s_sc[sp * SCS + k] = pack2(v.x, v.y);
    }

    // ---- accumulators for 1 channel: c = c0 + tid ----
    unsigned long long acc[KP];
    #pragma unroll
    for (int k = 0; k < KP; k++) acc[k] = 0ull;
    unsigned long long sum2 = 0ull;
    float2 mx = make_float2(-CUDART_INF_F, -CUDART_INF_F);

    const float4* g4 = (const float4*)(feat + ((size_t)n * C + c0) * HW);

    for (int ch = 0; ch < NCHUNK; ch++) {
        if (ch) __syncthreads();   // prev chunk fully consumed before overwrite

        // ---- stage feat chunk: 128 ch x 32 spatial -> transposed [sp-pair][c] ----
        // idx = tid + it*THREADS: cc = idx>>3 (channel), sq = idx&7 (float4 in chunk)
        #pragma unroll
        for (int it = 0; it < (CPB * 2 * SPC / 4) / THREADS; it++) {  // 8 iters
            int idx = tid + it * THREADS;
            int cc  = idx >> 3;
            int sq  = idx & 7;
            float4 v = g4[(size_t)cc * (HW / 4) + (ch * (SPC / 2) + sq)];
            s_ft[(2 * sq    ) * FSTRIDE + cc] = make_float2(v.x, v.y);
            s_ft[(2 * sq + 1) * FSTRIDE + cc] = make_float2(v.z, v.w);
        }
        __syncthreads();

        // ---- compute chunk: immediate smem offsets, broadcast score reads ----
        const unsigned long long* scb = s_sc + ch * SPC * SCS;
        #pragma unroll
        for (int spL = 0; spL < SPC; spL++) {
            float2 f = s_ft[spL * FSTRIDE + tid];
            unsigned long long fd = pack2(f.x, f.y);

            const ulonglong2* srow = (const ulonglong2*)(scb + spL * SCS);
            #pragma unroll
            for (int j = 0; j < 6; j++) {              // k = 2j, 2j+1 via LDS.128
                ulonglong2 q = srow[j];
                acc[2 * j    ] = fma2(fd, q.x, acc[2 * j    ]);
                acc[2 * j + 1] = fma2(fd, q.y, acc[2 * j + 1]);
            }
            acc[12] = fma2(fd, scb[spL * SCS + 12], acc[12]);

            sum2 = add2(sum2, fd);
            mx.x = fmaxf(mx.x, f.x);
            mx.y = fmaxf(mx.y, f.y);
        }
    }

    // ---- epilogue: 13 local sums + (mean + max) global ----
    const int c = c0 + tid;
    float* op = out_feat + (size_t)n * (KP + 1) * C;
    #pragma unroll
    for (int k = 0; k < KP; k++) {
        float2 a = unpack2(acc[k]);
        op[(size_t)k * C + c] = a.x + a.y;
    }
    float2 s = unpack2(sum2);
    op[(size_t)KP * C + c] = (s.x + s.y) * (1.0f / (float)HW) + fmaxf(mx.x, mx.y);
}

extern "C" void kernel_launch(void* const* d_in, const int* in_sizes, int n_in,
                              void* d_out, int out_size)
{
    const float* feat  = (const float*)d_in[0];
    const float* score = (const float*)d_in[1];
    const float* conf  = (const float*)d_in[2];
    float* out = (float*)d_out;

    const int N = in_sizes[2] / KP;                 // 256
    const int C = in_sizes[0] / ((size_t)N * HW);   // 2048

    float* out_feat = out;
    float* out_conf = out + (size_t)N * (KP + 1) * C;

    cudaFuncSetAttribute(horeid_kernel,
                         cudaFuncAttributeMaxDynamicSharedMemorySize, SMEM_BYTES);

    dim3 grid(C / CPB, N);
    horeid_kernel<<<grid, THREADS, SMEM_BYTES>>>(feat, score, conf,
                                                 out_feat, out_conf, C);
}

// round 7
// speedup vs baseline: 1.1756x; 1.1756x over previous
#include <cuda_runtime.h>
#include <cstdint>
#include <math_constants.h>

// feat [N, C, 16, 8], scoremap [N, 13, 16, 8], conf [N, 13]
#define KP        13
#define HW        128       // 16*8 spatial
#define CPB       256       // channels per block (2 per thread)
#define THREADS   128
#define SPCF      16        // spatial floats per chunk (= 4 float4, 8 sp-pairs)
#define NCHUNK    (HW / SPCF)   // 8
#define SCS       18        // u64 per score smem row (13 pad to 18: 144B, 16B-aligned)

#define SC_BYTES   (64 * SCS * 8)          // 9216
#define BUF_BYTES  (CPB * SPCF * 4)        // 16384 per buffer (64B per row)
#define SMEM_BYTES (SC_BYTES + 2 * BUF_BYTES)

// ---------- f32x2 helpers (Blackwell packed fp32) ----------
__device__ __forceinline__ unsigned long long pack2(float a, float b) {
    unsigned long long r;
    asm("mov.b64 %0, {%1, %2};" : "=l"(r) : "f"(a), "f"(b));
    return r;
}
__device__ __forceinline__ float2 unpack2(unsigned long long v) {
    float2 f;
    asm("mov.b64 {%0, %1}, %2;" : "=f"(f.x), "=f"(f.y) : "l"(v));
    return f;
}
__device__ __forceinline__ unsigned long long fma2(unsigned long long a,
                                                   unsigned long long b,
                                                   unsigned long long c) {
    unsigned long long d;
    asm("fma.rn.f32x2 %0, %1, %2, %3;" : "=l"(d) : "l"(a), "l"(b), "l"(c));
    return d;
}
__device__ __forceinline__ unsigned long long add2(unsigned long long a,
                                                   unsigned long long b) {
    unsigned long long d;
    asm("add.rn.f32x2 %0, %1, %2;" : "=l"(d) : "l"(a), "l"(b));
    return d;
}
__device__ __forceinline__ uint32_t smem_u32(const void* p) {
    return (uint32_t)__cvta_generic_to_shared(p);
}
__device__ __forceinline__ void cp16(uint32_t dst, const void* src) {
    asm volatile("cp.async.cg.shared.global [%0], [%1], 16;"
                 :: "r"(dst), "l"(src) : "memory");
}
__device__ __forceinline__ void cp_commit() {
    asm volatile("cp.async.commit_group;" ::: "memory");
}
__device__ __forceinline__ void cp_wait1() {
    asm volatile("cp.async.wait_group 1;" ::: "memory");
}
__device__ __forceinline__ float4 lds128(uint32_t a) {
    float4 v;
    asm volatile("ld.shared.v4.f32 {%0,%1,%2,%3}, [%4];"
                 : "=f"(v.x), "=f"(v.y), "=f"(v.z), "=f"(v.w) : "r"(a));
    return v;
}

__global__ __launch_bounds__(THREADS, 4)
void horeid_kernel(const float* __restrict__ feat,
                   const float* __restrict__ score,
                   const float* __restrict__ conf,
                   float* __restrict__ out_feat,   // [N, 14, C]
                   float* __restrict__ out_conf,   // [N, 14]
                   int C)
{
    extern __shared__ unsigned char smem_raw[];
    unsigned long long* s_sc = (unsigned long long*)smem_raw;        // [64][SCS]
    const uint32_t buf_base = smem_u32(smem_raw) + SC_BYTES;         // 2 buffers

    const int tid = threadIdx.x;
    const int n   = blockIdx.y;
    const int c0  = blockIdx.x * CPB;

    // ---- tiny conf normalization, one thread of blockIdx.x==0 ----
    if (blockIdx.x == 0 && tid == 0) {
        const float* cp = conf + (size_t)n * KP;
        float s = 0.0f;
        #pragma unroll
        for (int k = 0; k < KP; k++) s += fabsf(cp[k]);
        s = fmaxf(s, 1e-12f);
        float* oc = out_conf + (size_t)n * (KP + 1);
        #pragma unroll
        for (int k = 0; k < KP; k++) oc[k] = cp[k] / s;
        oc[KP] = 1.0f;
    }

    const float4* g4 = (const float4*)(feat + ((size_t)n * C + c0) * HW);

    // ---- prologue: issue cp.async for chunks 0 and 1 ----
    // chunk ch: 256 rows x 16 floats; piece p = tid + it*128: c = p>>2, q = p&3
    // dst swizzle: physical 16B unit = q ^ (c&3)   (row stride 64B, no pad)
    #pragma unroll
    for (int ch = 0; ch < 2; ch++) {
        uint32_t db = buf_base + ch * BUF_BYTES;
        #pragma unroll
        for (int it = 0; it < 8; it++) {
            int p = tid + it * THREADS;
            int c = p >> 2, q = p & 3;
            cp16(db + c * 64 + ((q ^ (c & 3)) << 4),
                 g4 + (size_t)c * (HW / 4) + ch * 4 + q);
        }
        cp_commit();
    }

    // ---- stage scoremap[n]: s_sc[sp][k] = (score[k][2sp], score[k][2sp+1]) ----
    const float2* g_sc = (const float2*)(score + (size_t)n * KP * HW);
    #pragma unroll
    for (int i = tid; i < KP * 64; i += THREADS) {
        int k  = i >> 6;
        int sp = i & 63;
        float2 v = g_sc[i];
        s_sc[sp * SCS + k] = pack2(v.x, v.y);
    }

    // ---- accumulators: cA = c0+tid, cB = cA+128 ----
    unsigned long long accA[KP], accB[KP];
    #pragma unroll
    for (int k = 0; k < KP; k++) { accA[k] = 0ull; accB[k] = 0ull; }
    unsigned long long sumA = 0ull, sumB = 0ull;
    float2 mxA = make_float2(-CUDART_INF_F, -CUDART_INF_F);
    float2 mxB = make_float2(-CUDART_INF_F, -CUDART_INF_F);

    const uint32_t m16 = (tid & 3) << 4;   // swizzle mask (same for tid and tid+128)

    for (int ch = 0; ch < NCHUNK; ch++) {
        cp_wait1();                 // chunk ch landed (ch+1 may remain in flight)
        __syncthreads();

        const uint32_t bb = buf_base + (ch & 1) * BUF_BYTES;
        const uint32_t aA = bb + tid * 64 + m16;            // channel A row
        const uint32_t aB = aA + 128 * 64;                  // channel B row
        const unsigned long long* scb = s_sc + ch * 8 * SCS;

        #pragma unroll
        for (int q = 0; q < 4; q++) {                       // 2 sp-pairs per q
            float4 fa = lds128(aA ^ (q << 4));
            float4 fb = lds128(aB ^ (q << 4));
            unsigned long long fa0 = pack2(fa.x, fa.y), fa1 = pack2(fa.z, fa.w);
            unsigned long long fb0 = pack2(fb.x, fb.y), fb1 = pack2(fb.z, fb.w);

            const ulonglong2* r0 = (const ulonglong2*)(scb + (2 * q    ) * SCS);
            const ulonglong2* r1 = (const ulonglong2*)(scb + (2 * q + 1) * SCS);
            #pragma unroll
            for (int j = 0; j < 6; j++) {
                ulonglong2 q0 = r0[j];
                ulonglong2 q1 = r1[j];
                accA[2*j  ] = fma2(fa1, q1.x, fma2(fa0, q0.x, accA[2*j  ]));
                accB[2*j  ] = fma2(fb1, q1.x, fma2(fb0, q0.x, accB[2*j  ]));
                accA[2*j+1] = fma2(fa1, q1.y, fma2(fa0, q0.y, accA[2*j+1]));
                accB[2*j+1] = fma2(fb1, q1.y, fma2(fb0, q0.y, accB[2*j+1]));
            }
            unsigned long long s120 = ((const unsigned long long*)r0)[12];
            unsigned long long s121 = ((const unsigned long long*)r1)[12];
            accA[12] = fma2(fa1, s121, fma2(fa0, s120, accA[12]));
            accB[12] = fma2(fb1, s121, fma2(fb0, s120, accB[12]));

            sumA = add2(sumA, add2(fa0, fa1));
            sumB = add2(sumB, add2(fb0, fb1));
            mxA.x = fmaxf(mxA.x, fmaxf(fa.x, fa.z));
            mxA.y = fmaxf(mxA.y, fmaxf(fa.y, fa.w));
            mxB.x = fmaxf(mxB.x, fmaxf(fb.x, fb.z));
            mxB.y = fmaxf(mxB.y, fmaxf(fb.y, fb.w));
        }

        __syncthreads();            // everyone done reading buf[ch&1]
        if (ch + 2 < NCHUNK) {      // refill it with chunk ch+2
            #pragma unroll
            for (int it = 0; it < 8; it++) {
                int p = tid + it * THREADS;
                int c = p >> 2, q = p & 3;
                cp16(bb + c * 64 + ((q ^ (c & 3)) << 4),
                     g4 + (size_t)c * (HW / 4) + (ch + 2) * 4 + q);
            }
        }
        cp_commit();                // empty groups near the tail keep counts uniform
    }

    // ---- epilogue: 13 local sums + (mean + max) global, both channels ----
    const int cA = c0 + tid;
    const int cB = cA + 128;
    float* op = out_feat + (size_t)n * (KP + 1) * C;
    #pragma unroll
    for (int k = 0; k < KP; k++) {
        float2 a = unpack2(accA[k]);
        float2 b = unpack2(accB[k]);
        op[(size_t)k * C + cA] = a.x + a.y;
        op[(size_t)k * C + cB] = b.x + b.y;
    }
    float2 sa = unpack2(sumA), sb = unpack2(sumB);
    op[(size_t)KP * C + cA] = (sa.x + sa.y) * (1.0f / (float)HW) + fmaxf(mxA.x, mxA.y);
    op[(size_t)KP * C + cB] = (sb.x + sb.y) * (1.0f / (float)HW) + fmaxf(mxB.x, mxB.y);
}

extern "C" void kernel_launch(void* const* d_in, const int* in_sizes, int n_in,
                              void* d_out, int out_size)
{
    const float* feat  = (const float*)d_in[0];
    const float* score = (const float*)d_in[1];
    const float* conf  = (const float*)d_in[2];
    float* out = (float*)d_out;

    const int N = in_sizes[2] / KP;                 // 256
    const int C = in_sizes[0] / ((size_t)N * HW);   // 2048

    float* out_feat = out;
    float* out_conf = out + (size_t)N * (KP + 1) * C;

    cudaFuncSetAttribute(horeid_kernel,
                         cudaFuncAttributeMaxDynamicSharedMemorySize, SMEM_BYTES);

    dim3 grid(C / CPB, N);
    horeid_kernel<<<grid, THREADS, SMEM_BYTES>>>(feat, score, conf,
                                                 out_feat, out_conf, C);
}

// round 8
// speedup vs baseline: 1.7871x; 1.5202x over previous
#include <cuda_runtime.h>
#include <cstdint>
#include <math_constants.h>

// feat [N, C, 16, 8], scoremap [N, 13, 16, 8], conf [N, 13]
#define KP        13
#define HW        128       // 16*8 spatial
#define CPB       256       // channels per block (2 per thread)
#define THREADS   128
#define SPCF      32        // spatial floats per chunk (8 float4, 16 sp-pairs)
#define NCHUNK    (HW / SPCF)   // 4
#define SCS       14        // u64 per score smem row (13 pad to 14: 112B, 16B-aligned)

#define SC_BYTES   (64 * SCS * 8)          // 7168
#define BUF_BYTES  (CPB * SPCF * 4)        // 32768 per buffer (128B per channel row)
#define SMEM_BYTES (SC_BYTES + 2 * BUF_BYTES)   // 72704

// ---------- f32x2 helpers (Blackwell packed fp32) ----------
__device__ __forceinline__ unsigned long long pack2(float a, float b) {
    unsigned long long r;
    asm("mov.b64 %0, {%1, %2};" : "=l"(r) : "f"(a), "f"(b));
    return r;
}
__device__ __forceinline__ float2 unpack2(unsigned long long v) {
    float2 f;
    asm("mov.b64 {%0, %1}, %2;" : "=f"(f.x), "=f"(f.y) : "l"(v));
    return f;
}
__device__ __forceinline__ unsigned long long fma2(unsigned long long a,
                                                   unsigned long long b,
                                                   unsigned long long c) {
    unsigned long long d;
    asm("fma.rn.f32x2 %0, %1, %2, %3;" : "=l"(d) : "l"(a), "l"(b), "l"(c));
    return d;
}
__device__ __forceinline__ unsigned long long add2(unsigned long long a,
                                                   unsigned long long b) {
    unsigned long long d;
    asm("add.rn.f32x2 %0, %1, %2;" : "=l"(d) : "l"(a), "l"(b));
    return d;
}
__device__ __forceinline__ uint32_t smem_u32(const void* p) {
    return (uint32_t)__cvta_generic_to_shared(p);
}
__device__ __forceinline__ void cp16(uint32_t dst, const float4* src) {
    asm volatile("cp.async.cg.shared.global [%0], [%1], 16;"
                 :: "r"(dst), "l"(src) : "memory");
}
__device__ __forceinline__ void cp_commit() {
    asm volatile("cp.async.commit_group;" ::: "memory");
}
__device__ __forceinline__ void cp_wait1() {
    asm volatile("cp.async.wait_group 1;" ::: "memory");
}
__device__ __forceinline__ float4 lds128(uint32_t a) {
    float4 v;
    asm volatile("ld.shared.v4.f32 {%0,%1,%2,%3}, [%4];"
                 : "=f"(v.x), "=f"(v.y), "=f"(v.z), "=f"(v.w) : "r"(a));
    return v;
}

__global__ __launch_bounds__(THREADS, 3)   // 3 blocks/SM (smem-capped); regs free to ~170
void horeid_kernel(const float* __restrict__ feat,
                   const float* __restrict__ score,
                   const float* __restrict__ conf,
                   float* __restrict__ out_feat,   // [N, 14, C]
                   float* __restrict__ out_conf,   // [N, 14]
                   int C)
{
    extern __shared__ unsigned char smem_raw[];
    unsigned long long* s_sc = (unsigned long long*)smem_raw;        // [64][SCS]
    const uint32_t buf_base = smem_u32(smem_raw) + SC_BYTES;         // 2 buffers

    const int tid = threadIdx.x;
    const int n   = blockIdx.y;
    const int c0  = blockIdx.x * CPB;

    const float4* g4 = (const float4*)(feat + ((size_t)n * C + c0) * HW);

    // Per-thread cp.async geometry (invariant across its/chunks):
    //   piece p = tid + it*128  ->  c = (tid>>3) + it*16,  q = tid&7 (constant)
    //   swizzle (q ^ (c&7)) is constant because it*16 === 0 (mod 8)
    const int qv = tid & 7;
    const int cb = tid >> 3;
    const uint32_t dst0 = cb * 128 + (uint32_t)((qv ^ (cb & 7)) << 4);
    const float4* src0 = g4 + (size_t)cb * (HW / 4) + qv;

    // ---- prologue: issue cp.async for chunks 0 and 1 ----
    #pragma unroll
    for (int ch = 0; ch < 2; ch++) {
        uint32_t dst = buf_base + ch * BUF_BYTES + dst0;
        const float4* src = src0 + ch * (SPCF / 4);
        #pragma unroll
        for (int it = 0; it < 16; it++) {
            cp16(dst, src);
            dst += 16 * 128;          // 16 channel rows
            src += 16 * (HW / 4);
        }
        cp_commit();
    }

    // ---- tiny conf normalization, one thread of blockIdx.x==0 ----
    if (blockIdx.x == 0 && tid == 0) {
        const float* cp = conf + (size_t)n * KP;
        float s = 0.0f;
        #pragma unroll
        for (int k = 0; k < KP; k++) s += fabsf(cp[k]);
        s = fmaxf(s, 1e-12f);
        float* oc = out_conf + (size_t)n * (KP + 1);
        #pragma unroll
        for (int k = 0; k < KP; k++) oc[k] = cp[k] / s;
        oc[KP] = 1.0f;
    }

    // ---- stage scoremap[n]: s_sc[sp][k] = (score[k][2sp], score[k][2sp+1]) ----
    const float2* g_sc = (const float2*)(score + (size_t)n * KP * HW);
    for (int i = tid; i < KP * 64; i += THREADS) {
        int k  = i >> 6;
        int sp = i & 63;
        float2 v = g_sc[i];
        s_sc[sp * SCS + k] = pack2(v.x, v.y);
    }

    // ---- accumulators: cA = c0+tid, cB = cA+128 ----
    unsigned long long accA[KP], accB[KP];
    #pragma unroll
    for (int k = 0; k < KP; k++) { accA[k] = 0ull; accB[k] = 0ull; }
    unsigned long long sumA = 0ull, sumB = 0ull;
    float2 mxA = make_float2(-CUDART_INF_F, -CUDART_INF_F);
    float2 mxB = make_float2(-CUDART_INF_F, -CUDART_INF_F);

    for (int ch = 0; ch < NCHUNK; ch++) {
        cp_wait1();                 // chunk ch landed (ch+1 may remain in flight)
        __syncthreads();

        const uint32_t bb   = buf_base + (ch & 1) * BUF_BYTES;
        const uint32_t rowA = bb + tid * 128;               // channel A row (128B)
        const unsigned long long* scb = s_sc + ch * 16 * SCS;

        #pragma unroll
        for (int q = 0; q < 8; q++) {                       // 2 sp-pairs per q
            uint32_t a = rowA + (uint32_t)(((q ^ qv)) << 4);
            float4 fa = lds128(a);
            float4 fb = lds128(a + 128 * 128);              // channel B row
            unsigned long long fa0 = pack2(fa.x, fa.y), fa1 = pack2(fa.z, fa.w);
            unsigned long long fb0 = pack2(fb.x, fb.y), fb1 = pack2(fb.z, fb.w);

            const ulonglong2* r0 = (const ulonglong2*)(scb + (2 * q    ) * SCS);
            const ulonglong2* r1 = (const ulonglong2*)(scb + (2 * q + 1) * SCS);
            #pragma unroll
            for (int j = 0; j < 6; j++) {
                ulonglong2 q0 = r0[j];
                ulonglong2 q1 = r1[j];
                accA[2*j  ] = fma2(fa0, q0.x, accA[2*j  ]);
                accA[2*j  ] = fma2(fa1, q1.x, accA[2*j  ]);
                accB[2*j  ] = fma2(fb0, q0.x, accB[2*j  ]);
                accB[2*j  ] = fma2(fb1, q1.x, accB[2*j  ]);
                accA[2*j+1] = fma2(fa0, q0.y, accA[2*j+1]);
                accA[2*j+1] = fma2(fa1, q1.y, accA[2*j+1]);
                accB[2*j+1] = fma2(fb0, q0.y, accB[2*j+1]);
                accB[2*j+1] = fma2(fb1, q1.y, accB[2*j+1]);
            }
            unsigned long long s120 = ((const unsigned long long*)r0)[12];
            unsigned long long s121 = ((const unsigned long long*)r1)[12];
            accA[12] = fma2(fa0, s120, accA[12]);
            accA[12] = fma2(fa1, s121, accA[12]);
            accB[12] = fma2(fb0, s120, accB[12]);
            accB[12] = fma2(fb1, s121, accB[12]);

            sumA = add2(sumA, add2(fa0, fa1));
            sumB = add2(sumB, add2(fb0, fb1));
            mxA.x = fmaxf(mxA.x, fmaxf(fa.x, fa.z));
            mxA.y = fmaxf(mxA.y, fmaxf(fa.y, fa.w));
            mxB.x = fmaxf(mxB.x, fmaxf(fb.x, fb.z));
            mxB.y = fmaxf(mxB.y, fmaxf(fb.y, fb.w));
        }

        __syncthreads();            // everyone done reading buf[ch&1]
        if (ch + 2 < NCHUNK) {      // refill it with chunk ch+2
            uint32_t dst = bb + dst0;
            const float4* src = src0 + (ch + 2) * (SPCF / 4);
            #pragma unroll
            for (int it = 0; it < 16; it++) {
                cp16(dst, src);
                dst += 16 * 128;
                src += 16 * (HW / 4);
            }
        }
        cp_commit();                // empty groups near tail keep counts uniform
    }

    // ---- epilogue: 13 local sums + (mean + max) global, both channels ----
    const int cA = c0 + tid;
    const int cB = cA + 128;
    float* op = out_feat + (size_t)n * (KP + 1) * C;
    #pragma unroll
    for (int k = 0; k < KP; k++) {
        float2 a = unpack2(accA[k]);
        float2 b = unpack2(accB[k]);
        op[(size_t)k * C + cA] = a.x + a.y;
        op[(size_t)k * C + cB] = b.x + b.y;
    }
    float2 sa = unpack2(sumA), sb = unpack2(sumB);
    op[(size_t)KP * C + cA] = (sa.x + sa.y) * (1.0f / (float)HW) + fmaxf(mxA.x, mxA.y);
    op[(size_t)KP * C + cB] = (sb.x + sb.y) * (1.0f / (float)HW) + fmaxf(mxB.x, mxB.y);
}

extern "C" void kernel_launch(void* const* d_in, const int* in_sizes, int n_in,
                              void* d_out, int out_size)
{
    const float* feat  = (const float*)d_in[0];
    const float* score = (const float*)d_in[1];
    const float* conf  = (const float*)d_in[2];
    float* out = (float*)d_out;

    const int N = in_sizes[2] / KP;                 // 256
    const int C = in_sizes[0] / ((size_t)N * HW);   // 2048

    float* out_feat = out;
    float* out_conf = out + (size_t)N * (KP + 1) * C;

    cudaFuncSetAttribute(horeid_kernel,
                         cudaFuncAttributeMaxDynamicSharedMemorySize, SMEM_BYTES);

    dim3 grid(C / CPB, N);
    horeid_kernel<<<grid, THREADS, SMEM_BYTES>>>(feat, score, conf,
                                                 out_feat, out_conf, C);
}

// round 9
// speedup vs baseline: 2.0884x; 1.1686x over previous
#include <cuda_runtime.h>
#include <cstdint>
#include <math_constants.h>

// feat [N, C, 16, 8], scoremap [N, 13, 16, 8], conf [N, 13]
#define KP        13
#define HW        128       // 16*8 spatial
#define CPB       256       // channels per block (2 per thread)
#define THREADS   128
#define SPCF      32        // spatial floats per chunk (8 float4, 16 sp-pairs)
#define NCHUNK    (HW / SPCF)   // 4

#define SC_BYTES   (KP * 64 * 8)           // 6656 (k-major raw score, u64[13][64])
#define BUF_BYTES  (CPB * SPCF * 4)        // 32768 per buffer (128B per channel row)
#define SMEM_BYTES (SC_BYTES + 2 * BUF_BYTES)   // 72192

// ---------- f32x2 helpers (Blackwell packed fp32) ----------
__device__ __forceinline__ unsigned long long pack2(float a, float b) {
    unsigned long long r;
    asm("mov.b64 %0, {%1, %2};" : "=l"(r) : "f"(a), "f"(b));
    return r;
}
__device__ __forceinline__ float2 unpack2(unsigned long long v) {
    float2 f;
    asm("mov.b64 {%0, %1}, %2;" : "=f"(f.x), "=f"(f.y) : "l"(v));
    return f;
}
__device__ __forceinline__ unsigned long long fma2(unsigned long long a,
                                                   unsigned long long b,
                                                   unsigned long long c) {
    unsigned long long d;
    asm("fma.rn.f32x2 %0, %1, %2, %3;" : "=l"(d) : "l"(a), "l"(b), "l"(c));
    return d;
}
__device__ __forceinline__ unsigned long long add2(unsigned long long a,
                                                   unsigned long long b) {
    unsigned long long d;
    asm("add.rn.f32x2 %0, %1, %2;" : "=l"(d) : "l"(a), "l"(b));
    return d;
}
__device__ __forceinline__ uint32_t smem_u32(const void* p) {
    return (uint32_t)__cvta_generic_to_shared(p);
}
__device__ __forceinline__ void cp16(uint32_t dst, const float4* src) {
    asm volatile("cp.async.cg.shared.global [%0], [%1], 16;"
                 :: "r"(dst), "l"(src) : "memory");
}
__device__ __forceinline__ void cp_commit() {
    asm volatile("cp.async.commit_group;" ::: "memory");
}
__device__ __forceinline__ void cp_wait1() {
    asm volatile("cp.async.wait_group 1;" ::: "memory");
}
__device__ __forceinline__ float4 lds128(uint32_t a) {
    float4 v;
    asm volatile("ld.shared.v4.f32 {%0,%1,%2,%3}, [%4];"
                 : "=f"(v.x), "=f"(v.y), "=f"(v.z), "=f"(v.w) : "r"(a));
    return v;
}
__device__ __forceinline__ ulonglong2 lds128u(uint32_t a) {
    ulonglong2 v;
    asm volatile("ld.shared.v2.u64 {%0,%1}, [%2];"
                 : "=l"(v.x), "=l"(v.y) : "r"(a));
    return v;
}

__global__ __launch_bounds__(THREADS, 3)   // 3 blocks/SM (smem-capped); regs free to ~170
void horeid_kernel(const float* __restrict__ feat,
                   const float* __restrict__ score,
                   const float* __restrict__ conf,
                   float* __restrict__ out_feat,   // [N, 14, C]
                   float* __restrict__ out_conf,   // [N, 14]
                   int C)
{
    extern __shared__ unsigned char smem_raw[];
    const uint32_t sc_base  = smem_u32(smem_raw);            // score u64[13][64]
    const uint32_t buf_base = sc_base + SC_BYTES;            // 2 feat buffers

    const int tid = threadIdx.x;
    const int n   = blockIdx.y;
    const int c0  = blockIdx.x * CPB;

    const float4* g4 = (const float4*)(feat + ((size_t)n * C + c0) * HW);

    // Per-thread cp.async geometry (invariant across its/chunks):
    //   piece p = tid + it*128  ->  c = (tid>>3) + it*16,  q = tid&7 (constant)
    //   swizzle (q ^ (c&7)) is constant because it*16 === 0 (mod 8)
    const int qv = tid & 7;
    const int cb = tid >> 3;
    const uint32_t dst0 = cb * 128 + (uint32_t)((qv ^ (cb & 7)) << 4);
    const float4* src0 = g4 + (size_t)cb * (HW / 4) + qv;

    // ---- prologue group A: score (k-major raw, 416 x 16B) + feat chunk 0 ----
    {
        const float4* gsc4 = (const float4*)(score + (size_t)n * KP * HW);
        #pragma unroll
        for (int it = 0; it < 4; it++) {
            int p = tid + it * THREADS;
            if (p < KP * HW / 4) cp16(sc_base + p * 16, gsc4 + p);
        }
        uint32_t dst = buf_base + dst0;
        const float4* src = src0;
        #pragma unroll
        for (int it = 0; it < 16; it++) {
            cp16(dst, src);
            dst += 16 * 128;          // 16 channel rows
            src += 16 * (HW / 4);
        }
        cp_commit();
    }
    // ---- prologue group B: feat chunk 1 ----
    {
        uint32_t dst = buf_base + BUF_BYTES + dst0;
        const float4* src = src0 + (SPCF / 4);
        #pragma unroll
        for (int it = 0; it < 16; it++) {
            cp16(dst, src);
            dst += 16 * 128;
            src += 16 * (HW / 4);
        }
        cp_commit();
    }

    // ---- tiny conf normalization, one thread of blockIdx.x==0 ----
    if (blockIdx.x == 0 && tid == 0) {
        const float* cp = conf + (size_t)n * KP;
        float s = 0.0f;
        #pragma unroll
        for (int k = 0; k < KP; k++) s += fabsf(cp[k]);
        s = fmaxf(s, 1e-12f);
        float* oc = out_conf + (size_t)n * (KP + 1);
        #pragma unroll
        for (int k = 0; k < KP; k++) oc[k] = cp[k] / s;
        oc[KP] = 1.0f;
    }

    // ---- accumulators: cA = c0+tid, cB = cA+128 ----
    unsigned long long accA[KP], accB[KP];
    #pragma unroll
    for (int k = 0; k < KP; k++) { accA[k] = 0ull; accB[k] = 0ull; }
    unsigned long long sumA = 0ull, sumB = 0ull;
    float2 mxA = make_float2(-CUDART_INF_F, -CUDART_INF_F);
    float2 mxB = make_float2(-CUDART_INF_F, -CUDART_INF_F);

    for (int ch = 0; ch < NCHUNK; ch++) {
        cp_wait1();                 // group for chunk ch landed (ch+1 may be in flight)
        __syncthreads();

        const uint32_t bb   = buf_base + (ch & 1) * BUF_BYTES;
        const uint32_t rowA = bb + tid * 128;               // channel A row (128B)
        // score byte addr for (k, sp0 = ch*16 + 2q): sc_base + k*512 + ch*128 + q*16
        const uint32_t scc  = sc_base + ch * 128;

        #pragma unroll
        for (int q = 0; q < 8; q++) {                       // 2 sp-pairs per q
            uint32_t a = rowA + (uint32_t)((q ^ qv) << 4);
            float4 fa = lds128(a);
            float4 fb = lds128(a + 128 * 128);              // channel B row
            unsigned long long fa0 = pack2(fa.x, fa.y), fa1 = pack2(fa.z, fa.w);
            unsigned long long fb0 = pack2(fb.x, fb.y), fb1 = pack2(fb.z, fb.w);

            const uint32_t sq = scc + (uint32_t)(q << 4);
            #pragma unroll
            for (int k = 0; k < KP; k++) {
                ulonglong2 s = lds128u(sq + k * 512);       // scores (sp0, sp0+1) for k
                accA[k] = fma2(fa0, s.x, accA[k]);
                accA[k] = fma2(fa1, s.y, accA[k]);
                accB[k] = fma2(fb0, s.x, accB[k]);
                accB[k] = fma2(fb1, s.y, accB[k]);
            }

            sumA = add2(sumA, add2(fa0, fa1));
            sumB = add2(sumB, add2(fb0, fb1));
            mxA.x = fmaxf(mxA.x, fmaxf(fa.x, fa.z));
            mxA.y = fmaxf(mxA.y, fmaxf(fa.y, fa.w));
            mxB.x = fmaxf(mxB.x, fmaxf(fb.x, fb.z));
            mxB.y = fmaxf(mxB.y, fmaxf(fb.y, fb.w));
        }

        __syncthreads();            // everyone done reading buf[ch&1]
        if (ch + 2 < NCHUNK) {      // refill it with chunk ch+2
            uint32_t dst = bb + dst0;
            const float4* src = src0 + (ch + 2) * (SPCF / 4);
            #pragma unroll
            for (int it = 0; it < 16; it++) {
                cp16(dst, src);
                dst += 16 * 128;
                src += 16 * (HW / 4);
            }
        }
        cp_commit();                // empty groups near tail keep counts uniform
    }

    // ---- epilogue: 13 local sums + (mean + max) global, both channels ----
    const int cA = c0 + tid;
    const int cB = cA + 128;
    float* op = out_feat + (size_t)n * (KP + 1) * C;
    #pragma unroll
    for (int k = 0; k < KP; k++) {
        float2 a = unpack2(accA[k]);
        float2 b = unpack2(accB[k]);
        op[(size_t)k * C + cA] = a.x + a.y;
        op[(size_t)k * C + cB] = b.x + b.y;
    }
    float2 sa = unpack2(sumA), sb = unpack2(sumB);
    op[(size_t)KP * C + cA] = (sa.x + sa.y) * (1.0f / (float)HW) + fmaxf(mxA.x, mxA.y);
    op[(size_t)KP * C + cB] = (sb.x + sb.y) * (1.0f / (float)HW) + fmaxf(mxB.x, mxB.y);
}

extern "C" void kernel_launch(void* const* d_in, const int* in_sizes, int n_in,
                              void* d_out, int out_size)
{
    const float* feat  = (const float*)d_in[0];
    const float* score = (const float*)d_in[1];
    const float* conf  = (const float*)d_in[2];
    float* out = (float*)d_out;

    const int N = in_sizes[2] / KP;                 // 256
    const int C = in_sizes[0] / ((size_t)N * HW);   // 2048

    float* out_feat = out;
    float* out_conf = out + (size_t)N * (KP + 1) * C;

    cudaFuncSetAttribute(horeid_kernel,
                         cudaFuncAttributeMaxDynamicSharedMemorySize, SMEM_BYTES);

    dim3 grid(C / CPB, N);
    horeid_kernel<<<grid, THREADS, SMEM_BYTES>>>(feat, score, conf,
                                                 out_feat, out_conf, C);
}